// round 6
// baseline (speedup 1.0000x reference)
#include <cuda_runtime.h>
#include <cuda_bf16.h>
#include <cstdint>

#define Bn  16
#define Tn  2048
#define Cn  384
#define DKn 64

// Pre-split bf16 operands
__device__ __align__(16) __nv_bfloat16 g_qhi [Bn * Tn * DKn];
__device__ __align__(16) __nv_bfloat16 g_qlo [Bn * Tn * DKn];
__device__ __align__(16) __nv_bfloat16 g_khi [Bn * Tn * DKn];
__device__ __align__(16) __nv_bfloat16 g_klo [Bn * Tn * DKn];
__device__ __align__(16) __nv_bfloat16 g_vthi[Bn * DKn * Tn];   // [b][d][t]
__device__ __align__(16) __nv_bfloat16 g_vtlo[Bn * DKn * Tn];
// Pre-transposed, pre-split weights: [n][k] with n in 0..191 = [Q|K|V]
__device__ __align__(16) __nv_bfloat16 g_wthi[192 * Cn];
__device__ __align__(16) __nv_bfloat16 g_wtlo[192 * Cn];

// ===================== helpers =====================
__device__ __forceinline__ uint32_t smem_u32(const void* p) {
    uint32_t a;
    asm("{ .reg .u64 t; cvta.to.shared.u64 t, %1; cvt.u32.u64 %0, t; }" : "=r"(a) : "l"(p));
    return a;
}
__device__ __forceinline__ uint32_t pack2(float e0, float e1) {
    uint32_t r;
    asm("cvt.rn.bf16x2.f32 %0, %1, %2;" : "=r"(r) : "f"(e1), "f"(e0));
    return r;
}
__device__ __forceinline__ void split2(float e0, float e1, uint32_t& hi, uint32_t& lo) {
    hi = pack2(e0, e1);
    float h0 = __uint_as_float(hi << 16);
    float h1 = __uint_as_float(hi & 0xffff0000u);
    lo = pack2(e0 - h0, e1 - h1);
}
__device__ __forceinline__ void ldsm4(uint32_t r[4], uint32_t addr) {
    asm volatile("ldmatrix.sync.aligned.m8n8.x4.shared.b16 {%0,%1,%2,%3}, [%4];"
        : "=r"(r[0]), "=r"(r[1]), "=r"(r[2]), "=r"(r[3]) : "r"(addr));
}
__device__ __forceinline__ void mma16816(float c[4], const uint32_t a[4],
                                         uint32_t b0, uint32_t b1) {
    asm volatile(
        "mma.sync.aligned.m16n8k16.row.col.f32.bf16.bf16.f32 "
        "{%0,%1,%2,%3},{%4,%5,%6,%7},{%8,%9},{%0,%1,%2,%3};"
        : "+f"(c[0]), "+f"(c[1]), "+f"(c[2]), "+f"(c[3])
        : "r"(a[0]), "r"(a[1]), "r"(a[2]), "r"(a[3]), "r"(b0), "r"(b1));
}
#define STS128(a, v) \
    asm volatile("st.shared.v4.b32 [%0], {%1,%2,%3,%4};" \
        :: "r"(a), "r"((v).x), "r"((v).y), "r"((v).z), "r"((v).w) : "memory")
#define STS64(a, r0, r1) \
    asm volatile("st.shared.v2.b32 [%0], {%1,%2};" :: "r"(a), "r"(r0), "r"(r1) : "memory")
#define CP16(sm, gp) \
    asm volatile("cp.async.cg.shared.global [%0], [%1], 16;" :: "r"(sm), "l"(gp) : "memory")
#define CP_COMMIT() asm volatile("cp.async.commit_group;" ::: "memory")
#define CP_WAIT(n)  asm volatile("cp.async.wait_group %0;" :: "n"(n) : "memory")

extern __shared__ __align__(16) char dsmem[];

// ===================== prep_w: transpose + split W once (coalesced) =========
// 18 blocks: (mat m, k-chunk c). Load 64k x 64n coalesced, smem transpose,
// write [n][k] coalesced.
__global__ __launch_bounds__(256) void prep_w(
    const float* __restrict__ WQ,
    const float* __restrict__ WK,
    const float* __restrict__ WV)
{
    __shared__ float sw[64][65];
    const int tid = threadIdx.x;
    const int m   = blockIdx.x / 6;
    const int kk  = (blockIdx.x % 6) * 64;
    const float* W = (m == 0) ? WQ : ((m == 1) ? WK : WV);

#pragma unroll
    for (int it = 0; it < 4; it++) {
        int idx = tid + (it << 8);
        int k = idx >> 4, n4 = (idx & 15) << 2;
        float4 v = *(const float4*)(W + (size_t)(kk + k) * DKn + n4);
        sw[k][n4] = v.x; sw[k][n4 + 1] = v.y; sw[k][n4 + 2] = v.z; sw[k][n4 + 3] = v.w;
    }
    __syncthreads();

#pragma unroll
    for (int it = 0; it < 2; it++) {
        int idx = tid + (it << 8);          // < 512
        int n = idx >> 3, k0 = (idx & 7) << 3;
        uint32_t h[4], lo[4];
#pragma unroll
        for (int j = 0; j < 4; j++)
            split2(sw[k0 + 2 * j][n], sw[k0 + 2 * j + 1][n], h[j], lo[j]);
        size_t off = (size_t)(m * 64 + n) * Cn + kk + k0;
        *(uint4*)(g_wthi + off) = make_uint4(h[0], h[1], h[2], h[3]);
        *(uint4*)(g_wtlo + off) = make_uint4(lo[0], lo[1], lo[2], lo[3]);
    }
}

// ===================== projection (bf16 3-term split, cp.async W) ==========
// smem: XS hi/lo 2x16KB @0; WT double buffer 2x48KB @32768 (hi +0, lo +24576)
#define P_XHI 0u
#define P_XLO 16384u
#define P_WT0 32768u
#define P_WSTRIDE 49152u
#define PROJ_SMEM (131072u + 128u)

__device__ __forceinline__ void stage_wt_async(uint32_t dst, int kk, int tid) {
#pragma unroll
    for (int i = 0; i < 6; i++) {            // 1536 = 192 rows x 8 units
        int idx = tid + (i << 8);
        int n = idx >> 3, u = idx & 7;
        uint32_t sw = (uint32_t)n * 128u + (uint32_t)((u ^ (n & 7)) << 4);
        CP16(dst + sw,          g_wthi + n * Cn + kk + (u << 3));
        CP16(dst + 24576u + sw, g_wtlo + n * Cn + kk + (u << 3));
    }
}

__global__ __launch_bounds__(256, 1) void proj_tc_kernel(const float* __restrict__ x)
{
    uint32_t raw = smem_u32(dsmem);
    uint32_t sb  = (raw + 127u) & ~127u;
    char*    bp  = dsmem + (sb - raw);
    float (*vt)[65] = (float(*)[65])(bp + P_WT0);   // epilogue overlay

    const int tid = threadIdx.x;
    const int w   = tid >> 5;
    const int l   = tid & 31;

    const int arow = (w << 4) + (l & 7) + (((l >> 3) & 1) << 3);
    const int brow = l & 7;
    const int bu   = l >> 3;

    for (int sel = 0; sel < 2; sel++) {
        const int r0 = (blockIdx.x + (sel << 7)) * 128;

        float acc[24][4];
#pragma unroll
        for (int i = 0; i < 24; i++)
#pragma unroll
            for (int j = 0; j < 4; j++) acc[i][j] = 0.f;

        stage_wt_async(sb + P_WT0, 0, tid);
        CP_COMMIT();

        for (int c = 0; c < Cn / 64; c++) {
            const int kk = c * 64;
            // ---- stage x chunk: LDG -> split -> STS (swizzled) ----
#pragma unroll
            for (int it = 0; it < 8; it++) {
                int idx = tid + (it << 8);
                int r = idx >> 4, k4 = (idx & 15) << 2;
                float4 v = *(const float4*)(x + (size_t)(r0 + r) * Cn + kk + k4);
                uint32_t h0, l0, h1, l1;
                split2(v.x, v.y, h0, l0);
                split2(v.z, v.w, h1, l1);
                uint32_t sw = (uint32_t)r * 128u
                            + (uint32_t)((((k4 >> 3) ^ (r & 7)) << 4))
                            + (uint32_t)((k4 & 7) << 1);
                STS64(sb + P_XHI + sw, h0, h1);
                STS64(sb + P_XLO + sw, l0, l1);
            }
            if (c + 1 < Cn / 64) {
                stage_wt_async(sb + P_WT0 + (uint32_t)((c + 1) & 1) * P_WSTRIDE,
                               kk + 64, tid);
                CP_COMMIT();
                CP_WAIT(1);
            } else {
                CP_WAIT(0);
            }
            __syncthreads();

            const uint32_t wtb = sb + P_WT0 + (uint32_t)(c & 1) * P_WSTRIDE;

            uint32_t ah[4][4], al[4][4];
            {
                uint32_t rb = sb + (uint32_t)arow * 128u;
#pragma unroll
                for (int ks = 0; ks < 4; ks++) {
                    int u = (ks << 1) + (l >> 4);
                    uint32_t sw = (uint32_t)((u ^ (arow & 7)) << 4);
                    ldsm4(ah[ks], rb + P_XHI + sw);
                    ldsm4(al[ks], rb + P_XLO + sw);
                }
            }
#pragma unroll
            for (int nt = 0; nt < 24; nt++) {
                int rowb = (nt << 3) + brow;
                uint32_t rb = wtb + (uint32_t)rowb * 128u;
                uint32_t s0 = (uint32_t)((bu       ^ (rowb & 7)) << 4);
                uint32_t s1 = (uint32_t)(((4 + bu) ^ (rowb & 7)) << 4);
                uint32_t bh[8], bl[8];
                ldsm4(bh,     rb + s0);
                ldsm4(bh + 4, rb + s1);
                ldsm4(bl,     rb + 24576u + s0);
                ldsm4(bl + 4, rb + 24576u + s1);
#pragma unroll
                for (int s = 0; s < 4; s++) {
                    mma16816(acc[nt], ah[s], bh[2 * s], bh[2 * s + 1]);
                    mma16816(acc[nt], ah[s], bl[2 * s], bl[2 * s + 1]);
                    mma16816(acc[nt], al[s], bh[2 * s], bh[2 * s + 1]);
                }
            }
            __syncthreads();
        }

        // ---- epilogue: Q (x0.125) / K split-store; V staged for transpose ----
        const int rl = (w << 4) + (l >> 2);
        const int cc = (l & 3) << 1;
        const size_t row0 = (size_t)(r0 + rl);
#pragma unroll
        for (int nt = 0; nt < 8; nt++) {
            int cidx = (nt << 3) + cc;
            uint32_t h, lo;
            split2(acc[nt][0] * 0.125f, acc[nt][1] * 0.125f, h, lo);
            *(uint32_t*)(g_qhi + row0 * 64 + cidx) = h;
            *(uint32_t*)(g_qlo + row0 * 64 + cidx) = lo;
            split2(acc[nt][2] * 0.125f, acc[nt][3] * 0.125f, h, lo);
            *(uint32_t*)(g_qhi + (row0 + 8) * 64 + cidx) = h;
            *(uint32_t*)(g_qlo + (row0 + 8) * 64 + cidx) = lo;

            split2(acc[nt + 8][0], acc[nt + 8][1], h, lo);
            *(uint32_t*)(g_khi + row0 * 64 + cidx) = h;
            *(uint32_t*)(g_klo + row0 * 64 + cidx) = lo;
            split2(acc[nt + 8][2], acc[nt + 8][3], h, lo);
            *(uint32_t*)(g_khi + (row0 + 8) * 64 + cidx) = h;
            *(uint32_t*)(g_klo + (row0 + 8) * 64 + cidx) = lo;

            vt[rl][cidx]         = acc[nt + 16][0];
            vt[rl][cidx + 1]     = acc[nt + 16][1];
            vt[rl + 8][cidx]     = acc[nt + 16][2];
            vt[rl + 8][cidx + 1] = acc[nt + 16][3];
        }
        __syncthreads();

        {
            const int b  = r0 >> 11;
            const int t0 = r0 & 2047;
            const int d  = tid >> 2;
            const int tq = (tid & 3) << 5;
#pragma unroll
            for (int g = 0; g < 8; g++) {
                int tl = tq + g * 4;
                float v0 = vt[tl][d], v1 = vt[tl + 1][d];
                float v2 = vt[tl + 2][d], v3 = vt[tl + 3][d];
                uint32_t h0, h1, l0, l1;
                split2(v0, v1, h0, l0);
                split2(v2, v3, h1, l1);
                size_t off = ((size_t)(b * DKn + d) << 11) + t0 + tl;
                *(uint2*)(g_vthi + off) = make_uint2(h0, h1);
                *(uint2*)(g_vtlo + off) = make_uint2(l0, l1);
            }
        }
        __syncthreads();   // protect vt overlay before next sel's W staging
    }
}

// ===================== attention (paired q-tiles, single wave) ==============
// smem: Q hi/lo 2x16KB @0; KV double buffer @32768, each 32KB:
//   KHI +0, KLO +8192, VHI +16384, VLO +24576; buffer stride 32768.
#define A_QHI 0u
#define A_QLO 16384u
#define A_KV0 32768u
#define A_KHI 0u
#define A_KLO 8192u
#define A_VHI 16384u
#define A_VLO 24576u
#define ATTN_SMEM (98304u + 128u)

__device__ __forceinline__ void stage_kv_async(uint32_t dst, int b, int ks, int tid) {
    const __nv_bfloat16* kh = g_khi + (((size_t)(b * Tn + ks)) << 6);
    const __nv_bfloat16* kl = g_klo + (((size_t)(b * Tn + ks)) << 6);
    const __nv_bfloat16* vh = g_vthi + (((size_t)(b * DKn)) << 11) + ks;
    const __nv_bfloat16* vl = g_vtlo + (((size_t)(b * DKn)) << 11) + ks;
#pragma unroll
    for (int i = 0; i < 2; i++) {
        int idx = tid + (i << 8);
        int r = idx >> 3, u = idx & 7;
        uint32_t sw = (uint32_t)r * 128u + (uint32_t)((u ^ (r & 7)) << 4);
        CP16(dst + A_KHI + sw, kh + (r << 6) + (u << 3));
        CP16(dst + A_KLO + sw, kl + (r << 6) + (u << 3));
        CP16(dst + A_VHI + sw, vh + ((size_t)r << 11) + (u << 3));
        CP16(dst + A_VLO + sw, vl + ((size_t)r << 11) + (u << 3));
    }
}

__global__ __launch_bounds__(256, 1) void attn_kernel(float* __restrict__ out)
{
    uint32_t raw = smem_u32(dsmem);
    uint32_t sb  = (raw + 127u) & ~127u;

    const int tid = threadIdx.x;
    const int w   = tid >> 5;
    const int l   = tid & 31;

    const int b    = blockIdx.x & 15;
    const int pair = blockIdx.x >> 4;       // 0..7

    const int brow = l & 7;
    const int bu   = l >> 3;

    for (int sel = 0; sel < 2; sel++) {
        const int qt = sel ? pair : (15 - pair);   // heavy tile first
        const int q0 = qt << 7;

        // prefetch first K/V tile while staging Q
        stage_kv_async(sb + A_KV0, b, 0, tid);
        CP_COMMIT();

        {
            const uint4* qh = (const uint4*)(g_qhi + (((size_t)(b * Tn + q0)) << 6));
            const uint4* ql = (const uint4*)(g_qlo + (((size_t)(b * Tn + q0)) << 6));
#pragma unroll
            for (int i = 0; i < 4; i++) {
                int idx = tid + (i << 8);
                int r = idx >> 3, u = idx & 7;
                uint32_t sw = (uint32_t)r * 128u + (uint32_t)((u ^ (r & 7)) << 4);
                uint4 vh = qh[idx], vl = ql[idx];
                STS128(sb + A_QHI + sw, vh);
                STS128(sb + A_QLO + sw, vl);
            }
        }
        __syncthreads();

        uint32_t qh[4][4], qlr[4][4];
        {
            int arow = (w << 4) + (l & 7) + (((l >> 3) & 1) << 3);
            uint32_t rb = sb + (uint32_t)arow * 128u;
#pragma unroll
            for (int kk = 0; kk < 4; kk++) {
                int u = (kk << 1) + (l >> 4);
                uint32_t sw = (uint32_t)((u ^ (arow & 7)) << 4);
                ldsm4(qh[kk],  rb + A_QHI + sw);
                ldsm4(qlr[kk], rb + A_QLO + sw);
            }
        }

        float m0 = -3.0e38f, m1 = -3.0e38f, ls0 = 0.f, ls1 = 0.f;
        float o[8][4];
#pragma unroll
        for (int i = 0; i < 8; i++)
#pragma unroll
            for (int j = 0; j < 4; j++) o[i][j] = 0.f;

        const int kend  = q0 + 128;
        const int wrow0 = q0 + (w << 4);

        int it = 0;
        for (int ks = 0; ks < kend; ks += 64, it++) {
            if (ks + 64 < kend) {
                stage_kv_async(sb + A_KV0 + (uint32_t)((it + 1) & 1) * 32768u,
                               b, ks + 64, tid);
                CP_COMMIT();
                CP_WAIT(1);
            } else {
                CP_WAIT(0);
            }
            __syncthreads();

            const uint32_t kvb = sb + A_KV0 + (uint32_t)(it & 1) * 32768u;

            if (ks <= wrow0 + 15) {
                float sc[8][4];
#pragma unroll
                for (int nt = 0; nt < 8; nt++) {
                    int row = (nt << 3) + brow;
                    uint32_t rb = kvb + (uint32_t)row * 128u;
                    uint32_t s0 = (uint32_t)((bu       ^ (row & 7)) << 4);
                    uint32_t s1 = (uint32_t)(((4 + bu) ^ (row & 7)) << 4);
                    uint32_t kh8[8], kl8[8];
                    ldsm4(kh8,     rb + A_KHI + s0);
                    ldsm4(kh8 + 4, rb + A_KHI + s1);
                    ldsm4(kl8,     rb + A_KLO + s0);
                    ldsm4(kl8 + 4, rb + A_KLO + s1);
#pragma unroll
                    for (int j = 0; j < 4; j++) sc[nt][j] = 0.f;
#pragma unroll
                    for (int s = 0; s < 4; s++) {
                        mma16816(sc[nt], qh[s],  kh8[2 * s], kh8[2 * s + 1]);
                        mma16816(sc[nt], qh[s],  kl8[2 * s], kl8[2 * s + 1]);
                        mma16816(sc[nt], qlr[s], kh8[2 * s], kh8[2 * s + 1]);
                    }
                }

                const int R0 = wrow0 + (l >> 2);
                if (ks + 64 > wrow0) {
                    int colb = ks + ((l & 3) << 1);
#pragma unroll
                    for (int nt = 0; nt < 8; nt++) {
                        int c0 = colb + (nt << 3);
                        if (c0     > R0)     sc[nt][0] = -3.0e38f;
                        if (c0 + 1 > R0)     sc[nt][1] = -3.0e38f;
                        if (c0     > R0 + 8) sc[nt][2] = -3.0e38f;
                        if (c0 + 1 > R0 + 8) sc[nt][3] = -3.0e38f;
                    }
                }

                float tm0 = -3.0e38f, tm1 = -3.0e38f;
#pragma unroll
                for (int nt = 0; nt < 8; nt++) {
                    tm0 = fmaxf(tm0, fmaxf(sc[nt][0], sc[nt][1]));
                    tm1 = fmaxf(tm1, fmaxf(sc[nt][2], sc[nt][3]));
                }
                tm0 = fmaxf(tm0, __shfl_xor_sync(0xffffffffu, tm0, 1));
                tm0 = fmaxf(tm0, __shfl_xor_sync(0xffffffffu, tm0, 2));
                tm1 = fmaxf(tm1, __shfl_xor_sync(0xffffffffu, tm1, 1));
                tm1 = fmaxf(tm1, __shfl_xor_sync(0xffffffffu, tm1, 2));
                float mn0 = fmaxf(m0, tm0), mn1 = fmaxf(m1, tm1);
                float c0 = __expf(m0 - mn0), c1 = __expf(m1 - mn1);

                float ps0 = 0.f, ps1 = 0.f;
                uint32_t phi[4][4], plo[4][4];
#pragma unroll
                for (int s = 0; s < 4; s++) {
#pragma unroll
                    for (int h = 0; h < 2; h++) {
                        int nt = 2 * s + h;
                        float p0 = __expf(sc[nt][0] - mn0);
                        float p1 = __expf(sc[nt][1] - mn0);
                        float p2 = __expf(sc[nt][2] - mn1);
                        float p3 = __expf(sc[nt][3] - mn1);
                        ps0 += p0 + p1;
                        ps1 += p2 + p3;
                        split2(p0, p1, phi[s][2 * h],     plo[s][2 * h]);
                        split2(p2, p3, phi[s][2 * h + 1], plo[s][2 * h + 1]);
                    }
                }
                ps0 += __shfl_xor_sync(0xffffffffu, ps0, 1);
                ps0 += __shfl_xor_sync(0xffffffffu, ps0, 2);
                ps1 += __shfl_xor_sync(0xffffffffu, ps1, 1);
                ps1 += __shfl_xor_sync(0xffffffffu, ps1, 2);
                ls0 = ls0 * c0 + ps0;
                ls1 = ls1 * c1 + ps1;
                m0 = mn0; m1 = mn1;

#pragma unroll
                for (int nt = 0; nt < 8; nt++) {
                    o[nt][0] *= c0; o[nt][1] *= c0;
                    o[nt][2] *= c1; o[nt][3] *= c1;
                }
#pragma unroll
                for (int nt = 0; nt < 8; nt++) {
                    int row = (nt << 3) + brow;
                    uint32_t rb = kvb + (uint32_t)row * 128u;
                    uint32_t s0 = (uint32_t)((bu       ^ (row & 7)) << 4);
                    uint32_t s1 = (uint32_t)(((4 + bu) ^ (row & 7)) << 4);
                    uint32_t vh8[8], vl8[8];
                    ldsm4(vh8,     rb + A_VHI + s0);
                    ldsm4(vh8 + 4, rb + A_VHI + s1);
                    ldsm4(vl8,     rb + A_VLO + s0);
                    ldsm4(vl8 + 4, rb + A_VLO + s1);
#pragma unroll
                    for (int s = 0; s < 4; s++) {
                        mma16816(o[nt], phi[s], vh8[2 * s], vh8[2 * s + 1]);
                        mma16816(o[nt], phi[s], vl8[2 * s], vl8[2 * s + 1]);
                        mma16816(o[nt], plo[s], vh8[2 * s], vh8[2 * s + 1]);
                    }
                }
            }
            __syncthreads();
        }

        const float inv0 = 1.f / ls0, inv1 = 1.f / ls1;
        const int R0g = q0 + (w << 4) + (l >> 2);
        float* o0p = out + (((size_t)(b * Tn + R0g)) << 6) + ((l & 3) << 1);
        float* o1p = o0p + (8 << 6);
#pragma unroll
        for (int nt = 0; nt < 8; nt++) {
            *(float2*)(o0p + (nt << 3)) = make_float2(o[nt][0] * inv0, o[nt][1] * inv0);
            *(float2*)(o1p + (nt << 3)) = make_float2(o[nt][2] * inv1, o[nt][3] * inv1);
        }
    }
}

// ===================== launch =====================
extern "C" void kernel_launch(void* const* d_in, const int* in_sizes, int n_in,
                              void* d_out, int out_size)
{
    const float* x  = (const float*)d_in[0];
    const float* WQ = (const float*)d_in[1];
    const float* WK = (const float*)d_in[2];
    const float* WV = (const float*)d_in[3];
    float* out = (float*)d_out;

    cudaFuncSetAttribute(proj_tc_kernel,
                         cudaFuncAttributeMaxDynamicSharedMemorySize, PROJ_SMEM);
    cudaFuncSetAttribute(attn_kernel,
                         cudaFuncAttributeMaxDynamicSharedMemorySize, ATTN_SMEM);

    prep_w<<<18, 256>>>(WQ, WK, WV);
    proj_tc_kernel<<<128, 256, PROJ_SMEM>>>(x);
    attn_kernel<<<128, 256, ATTN_SMEM>>>(out);
}

// round 7
// speedup vs baseline: 1.0577x; 1.0577x over previous
#include <cuda_runtime.h>
#include <cuda_bf16.h>
#include <cstdint>

#define Bn  16
#define Tn  2048
#define Cn  384
#define DKn 64

// Pre-split bf16 operands
__device__ __align__(16) __nv_bfloat16 g_qhi [Bn * Tn * DKn];
__device__ __align__(16) __nv_bfloat16 g_qlo [Bn * Tn * DKn];
__device__ __align__(16) __nv_bfloat16 g_khi [Bn * Tn * DKn];
__device__ __align__(16) __nv_bfloat16 g_klo [Bn * Tn * DKn];
__device__ __align__(16) __nv_bfloat16 g_vthi[Bn * DKn * Tn];   // [b][d][t]
__device__ __align__(16) __nv_bfloat16 g_vtlo[Bn * DKn * Tn];
// Pre-transposed, pre-split weights: [n][k] with n in 0..191 = [Q|K|V]
__device__ __align__(16) __nv_bfloat16 g_wthi[192 * Cn];
__device__ __align__(16) __nv_bfloat16 g_wtlo[192 * Cn];

// ===================== helpers =====================
__device__ __forceinline__ uint32_t smem_u32(const void* p) {
    uint32_t a;
    asm("{ .reg .u64 t; cvta.to.shared.u64 t, %1; cvt.u32.u64 %0, t; }" : "=r"(a) : "l"(p));
    return a;
}
__device__ __forceinline__ uint32_t pack2(float e0, float e1) {
    uint32_t r;
    asm("cvt.rn.bf16x2.f32 %0, %1, %2;" : "=r"(r) : "f"(e1), "f"(e0));
    return r;
}
__device__ __forceinline__ void split2(float e0, float e1, uint32_t& hi, uint32_t& lo) {
    hi = pack2(e0, e1);
    float h0 = __uint_as_float(hi << 16);
    float h1 = __uint_as_float(hi & 0xffff0000u);
    lo = pack2(e0 - h0, e1 - h1);
}
__device__ __forceinline__ void ldsm4(uint32_t r[4], uint32_t addr) {
    asm volatile("ldmatrix.sync.aligned.m8n8.x4.shared.b16 {%0,%1,%2,%3}, [%4];"
        : "=r"(r[0]), "=r"(r[1]), "=r"(r[2]), "=r"(r[3]) : "r"(addr));
}
__device__ __forceinline__ void mma16816(float c[4], const uint32_t a[4],
                                         uint32_t b0, uint32_t b1) {
    asm volatile(
        "mma.sync.aligned.m16n8k16.row.col.f32.bf16.bf16.f32 "
        "{%0,%1,%2,%3},{%4,%5,%6,%7},{%8,%9},{%0,%1,%2,%3};"
        : "+f"(c[0]), "+f"(c[1]), "+f"(c[2]), "+f"(c[3])
        : "r"(a[0]), "r"(a[1]), "r"(a[2]), "r"(a[3]), "r"(b0), "r"(b1));
}
#define STS128(a, v) \
    asm volatile("st.shared.v4.b32 [%0], {%1,%2,%3,%4};" \
        :: "r"(a), "r"((v).x), "r"((v).y), "r"((v).z), "r"((v).w) : "memory")
#define STS64(a, r0, r1) \
    asm volatile("st.shared.v2.b32 [%0], {%1,%2};" :: "r"(a), "r"(r0), "r"(r1) : "memory")
#define CP16(sm, gp) \
    asm volatile("cp.async.cg.shared.global [%0], [%1], 16;" :: "r"(sm), "l"(gp) : "memory")
#define CP_COMMIT() asm volatile("cp.async.commit_group;" ::: "memory")
#define CP_WAIT(n)  asm volatile("cp.async.wait_group %0;" :: "n"(n) : "memory")

extern __shared__ __align__(16) char dsmem[];

// ===================== prep_w: transpose + split W once (coalesced) =========
__global__ __launch_bounds__(256) void prep_w(
    const float* __restrict__ WQ,
    const float* __restrict__ WK,
    const float* __restrict__ WV)
{
    __shared__ float sw[64][65];
    const int tid = threadIdx.x;
    const int m   = blockIdx.x / 6;
    const int kk  = (blockIdx.x % 6) * 64;
    const float* W = (m == 0) ? WQ : ((m == 1) ? WK : WV);

#pragma unroll
    for (int it = 0; it < 4; it++) {
        int idx = tid + (it << 8);
        int k = idx >> 4, n4 = (idx & 15) << 2;
        float4 v = *(const float4*)(W + (size_t)(kk + k) * DKn + n4);
        sw[k][n4] = v.x; sw[k][n4 + 1] = v.y; sw[k][n4 + 2] = v.z; sw[k][n4 + 3] = v.w;
    }
    __syncthreads();

#pragma unroll
    for (int it = 0; it < 2; it++) {
        int idx = tid + (it << 8);
        int n = idx >> 3, k0 = (idx & 7) << 3;
        uint32_t h[4], lo[4];
#pragma unroll
        for (int j = 0; j < 4; j++)
            split2(sw[k0 + 2 * j][n], sw[k0 + 2 * j + 1][n], h[j], lo[j]);
        size_t off = (size_t)(m * 64 + n) * Cn + kk + k0;
        *(uint4*)(g_wthi + off) = make_uint4(h[0], h[1], h[2], h[3]);
        *(uint4*)(g_wtlo + off) = make_uint4(lo[0], lo[1], lo[2], lo[3]);
    }
}

// ===================== projection (round-5 form: 256 CTAs, one tile each) ===
#define P_XHI 0u
#define P_XLO 16384u
#define P_WT0 32768u
#define P_WSTRIDE 49152u
#define PROJ_SMEM (131072u + 128u)

__device__ __forceinline__ void stage_wt_async(uint32_t dst, int kk, int tid) {
#pragma unroll
    for (int i = 0; i < 6; i++) {
        int idx = tid + (i << 8);
        int n = idx >> 3, u = idx & 7;
        uint32_t sw = (uint32_t)n * 128u + (uint32_t)((u ^ (n & 7)) << 4);
        CP16(dst + sw,          g_wthi + n * Cn + kk + (u << 3));
        CP16(dst + 24576u + sw, g_wtlo + n * Cn + kk + (u << 3));
    }
}

__global__ __launch_bounds__(256, 1) void proj_tc_kernel(const float* __restrict__ x)
{
    uint32_t raw = smem_u32(dsmem);
    uint32_t sb  = (raw + 127u) & ~127u;
    char*    bp  = dsmem + (sb - raw);
    float (*vt)[65] = (float(*)[65])(bp + P_WT0);

    const int tid = threadIdx.x;
    const int w   = tid >> 5;
    const int l   = tid & 31;
    const int r0  = blockIdx.x * 128;

    float acc[24][4];
#pragma unroll
    for (int i = 0; i < 24; i++)
#pragma unroll
        for (int j = 0; j < 4; j++) acc[i][j] = 0.f;

    const int arow = (w << 4) + (l & 7) + (((l >> 3) & 1) << 3);
    const int brow = l & 7;
    const int bu   = l >> 3;

    stage_wt_async(sb + P_WT0, 0, tid);
    CP_COMMIT();

    for (int c = 0; c < Cn / 64; c++) {
        const int kk = c * 64;
#pragma unroll
        for (int it = 0; it < 8; it++) {
            int idx = tid + (it << 8);
            int r = idx >> 4, k4 = (idx & 15) << 2;
            float4 v = *(const float4*)(x + (size_t)(r0 + r) * Cn + kk + k4);
            uint32_t h0, l0, h1, l1;
            split2(v.x, v.y, h0, l0);
            split2(v.z, v.w, h1, l1);
            uint32_t sw = (uint32_t)r * 128u
                        + (uint32_t)((((k4 >> 3) ^ (r & 7)) << 4))
                        + (uint32_t)((k4 & 7) << 1);
            STS64(sb + P_XHI + sw, h0, h1);
            STS64(sb + P_XLO + sw, l0, l1);
        }
        if (c + 1 < Cn / 64) {
            stage_wt_async(sb + P_WT0 + (uint32_t)((c + 1) & 1) * P_WSTRIDE,
                           kk + 64, tid);
            CP_COMMIT();
            CP_WAIT(1);
        } else {
            CP_WAIT(0);
        }
        __syncthreads();

        const uint32_t wtb = sb + P_WT0 + (uint32_t)(c & 1) * P_WSTRIDE;

        uint32_t ah[4][4], al[4][4];
        {
            uint32_t rb = sb + (uint32_t)arow * 128u;
#pragma unroll
            for (int ks = 0; ks < 4; ks++) {
                int u = (ks << 1) + (l >> 4);
                uint32_t sw = (uint32_t)((u ^ (arow & 7)) << 4);
                ldsm4(ah[ks], rb + P_XHI + sw);
                ldsm4(al[ks], rb + P_XLO + sw);
            }
        }
#pragma unroll
        for (int nt = 0; nt < 24; nt++) {
            int rowb = (nt << 3) + brow;
            uint32_t rb = wtb + (uint32_t)rowb * 128u;
            uint32_t s0 = (uint32_t)((bu       ^ (rowb & 7)) << 4);
            uint32_t s1 = (uint32_t)(((4 + bu) ^ (rowb & 7)) << 4);
            uint32_t bh[8], bl[8];
            ldsm4(bh,     rb + s0);
            ldsm4(bh + 4, rb + s1);
            ldsm4(bl,     rb + 24576u + s0);
            ldsm4(bl + 4, rb + 24576u + s1);
#pragma unroll
            for (int s = 0; s < 4; s++) {
                mma16816(acc[nt], ah[s], bh[2 * s], bh[2 * s + 1]);
                mma16816(acc[nt], ah[s], bl[2 * s], bl[2 * s + 1]);
                mma16816(acc[nt], al[s], bh[2 * s], bh[2 * s + 1]);
            }
        }
        __syncthreads();
    }

    const int rl = (w << 4) + (l >> 2);
    const int cc = (l & 3) << 1;
    const size_t row0 = (size_t)(r0 + rl);
#pragma unroll
    for (int nt = 0; nt < 8; nt++) {
        int cidx = (nt << 3) + cc;
        uint32_t h, lo;
        split2(acc[nt][0] * 0.125f, acc[nt][1] * 0.125f, h, lo);
        *(uint32_t*)(g_qhi + row0 * 64 + cidx) = h;
        *(uint32_t*)(g_qlo + row0 * 64 + cidx) = lo;
        split2(acc[nt][2] * 0.125f, acc[nt][3] * 0.125f, h, lo);
        *(uint32_t*)(g_qhi + (row0 + 8) * 64 + cidx) = h;
        *(uint32_t*)(g_qlo + (row0 + 8) * 64 + cidx) = lo;

        split2(acc[nt + 8][0], acc[nt + 8][1], h, lo);
        *(uint32_t*)(g_khi + row0 * 64 + cidx) = h;
        *(uint32_t*)(g_klo + row0 * 64 + cidx) = lo;
        split2(acc[nt + 8][2], acc[nt + 8][3], h, lo);
        *(uint32_t*)(g_khi + (row0 + 8) * 64 + cidx) = h;
        *(uint32_t*)(g_klo + (row0 + 8) * 64 + cidx) = lo;

        vt[rl][cidx]         = acc[nt + 16][0];
        vt[rl][cidx + 1]     = acc[nt + 16][1];
        vt[rl + 8][cidx]     = acc[nt + 16][2];
        vt[rl + 8][cidx + 1] = acc[nt + 16][3];
    }
    __syncthreads();

    {
        const int b  = r0 >> 11;
        const int t0 = r0 & 2047;
        const int d  = tid >> 2;
        const int tq = (tid & 3) << 5;
#pragma unroll
        for (int g = 0; g < 8; g++) {
            int tl = tq + g * 4;
            float v0 = vt[tl][d], v1 = vt[tl + 1][d];
            float v2 = vt[tl + 2][d], v3 = vt[tl + 3][d];
            uint32_t h0, h1, l0, l1;
            split2(v0, v1, h0, l0);
            split2(v2, v3, h1, l1);
            size_t off = ((size_t)(b * DKn + d) << 11) + t0 + tl;
            *(uint2*)(g_vthi + off) = make_uint2(h0, h1);
            *(uint2*)(g_vtlo + off) = make_uint2(l0, l1);
        }
    }
}

// ===================== attention (128 threads, 64-row q-tiles, 2 CTAs/SM) ===
// smem: Q hi 8KB @0, Q lo 8KB @8192; KV double buffer @16384, each 32KB:
//   KHI +0, KLO +8192, VHI +16384, VLO +24576; buffer stride 32768.
#define A_QHI 0u
#define A_QLO 8192u
#define A_KV0 16384u
#define A_KHI 0u
#define A_KLO 8192u
#define A_VHI 16384u
#define A_VLO 24576u
#define ATTN_SMEM (81920u + 128u)

__device__ __forceinline__ void stage_kv_async(uint32_t dst, int b, int ks, int tid) {
    const __nv_bfloat16* kh = g_khi + (((size_t)(b * Tn + ks)) << 6);
    const __nv_bfloat16* kl = g_klo + (((size_t)(b * Tn + ks)) << 6);
    const __nv_bfloat16* vh = g_vthi + (((size_t)(b * DKn)) << 11) + ks;
    const __nv_bfloat16* vl = g_vtlo + (((size_t)(b * DKn)) << 11) + ks;
#pragma unroll
    for (int i = 0; i < 4; i++) {
        int idx = tid + (i << 7);            // 512 units = 64 rows x 8
        int r = idx >> 3, u = idx & 7;
        uint32_t sw = (uint32_t)r * 128u + (uint32_t)((u ^ (r & 7)) << 4);
        CP16(dst + A_KHI + sw, kh + (r << 6) + (u << 3));
        CP16(dst + A_KLO + sw, kl + (r << 6) + (u << 3));
        CP16(dst + A_VHI + sw, vh + ((size_t)r << 11) + (u << 3));
        CP16(dst + A_VLO + sw, vl + ((size_t)r << 11) + (u << 3));
    }
}

__global__ __launch_bounds__(128, 2) void attn_kernel(float* __restrict__ out)
{
    uint32_t raw = smem_u32(dsmem);
    uint32_t sb  = (raw + 127u) & ~127u;

    const int tid = threadIdx.x;
    const int w   = tid >> 5;               // 0..3
    const int l   = tid & 31;

    const int bx = blockIdx.x;
    const int qt = 31 - (bx >> 4);           // heavy q-tiles first
    const int b  = bx & 15;
    const int q0 = qt << 6;

    // prefetch first K/V tile while staging Q
    stage_kv_async(sb + A_KV0, b, 0, tid);
    CP_COMMIT();

    {
        const uint4* qh = (const uint4*)(g_qhi + (((size_t)(b * Tn + q0)) << 6));
        const uint4* ql = (const uint4*)(g_qlo + (((size_t)(b * Tn + q0)) << 6));
#pragma unroll
        for (int i = 0; i < 4; i++) {
            int idx = tid + (i << 7);        // 512 = 64 rows x 8
            int r = idx >> 3, u = idx & 7;
            uint32_t sw = (uint32_t)r * 128u + (uint32_t)((u ^ (r & 7)) << 4);
            uint4 vh = qh[idx], vl = ql[idx];
            STS128(sb + A_QHI + sw, vh);
            STS128(sb + A_QLO + sw, vl);
        }
    }
    __syncthreads();

    uint32_t qh[4][4], qlr[4][4];
    {
        int arow = (w << 4) + (l & 7) + (((l >> 3) & 1) << 3);   // 0..63
        uint32_t rb = sb + (uint32_t)arow * 128u;
#pragma unroll
        for (int kk = 0; kk < 4; kk++) {
            int u = (kk << 1) + (l >> 4);
            uint32_t sw = (uint32_t)((u ^ (arow & 7)) << 4);
            ldsm4(qh[kk],  rb + A_QHI + sw);
            ldsm4(qlr[kk], rb + A_QLO + sw);
        }
    }

    float m0 = -3.0e38f, m1 = -3.0e38f, ls0 = 0.f, ls1 = 0.f;
    float o[8][4];
#pragma unroll
    for (int i = 0; i < 8; i++)
#pragma unroll
        for (int j = 0; j < 4; j++) o[i][j] = 0.f;

    const int kend  = q0 + 64;
    const int wrow0 = q0 + (w << 4);
    const int brow  = l & 7;
    const int bu    = l >> 3;

    int it = 0;
    for (int ks = 0; ks < kend; ks += 64, it++) {
        if (ks + 64 < kend) {
            stage_kv_async(sb + A_KV0 + (uint32_t)((it + 1) & 1) * 32768u,
                           b, ks + 64, tid);
            CP_COMMIT();
            CP_WAIT(1);
        } else {
            CP_WAIT(0);
        }
        __syncthreads();

        const uint32_t kvb = sb + A_KV0 + (uint32_t)(it & 1) * 32768u;

        if (ks <= wrow0 + 15) {
            float sc[8][4];
#pragma unroll
            for (int nt = 0; nt < 8; nt++) {
                int row = (nt << 3) + brow;
                uint32_t rb = kvb + (uint32_t)row * 128u;
                uint32_t s0 = (uint32_t)((bu       ^ (row & 7)) << 4);
                uint32_t s1 = (uint32_t)(((4 + bu) ^ (row & 7)) << 4);
                uint32_t kh8[8], kl8[8];
                ldsm4(kh8,     rb + A_KHI + s0);
                ldsm4(kh8 + 4, rb + A_KHI + s1);
                ldsm4(kl8,     rb + A_KLO + s0);
                ldsm4(kl8 + 4, rb + A_KLO + s1);
#pragma unroll
                for (int j = 0; j < 4; j++) sc[nt][j] = 0.f;
#pragma unroll
                for (int s = 0; s < 4; s++) {
                    mma16816(sc[nt], qh[s],  kh8[2 * s], kh8[2 * s + 1]);
                    mma16816(sc[nt], qh[s],  kl8[2 * s], kl8[2 * s + 1]);
                    mma16816(sc[nt], qlr[s], kh8[2 * s], kh8[2 * s + 1]);
                }
            }

            const int R0 = wrow0 + (l >> 2);
            if (ks + 64 > wrow0) {
                int colb = ks + ((l & 3) << 1);
#pragma unroll
                for (int nt = 0; nt < 8; nt++) {
                    int c0 = colb + (nt << 3);
                    if (c0     > R0)     sc[nt][0] = -3.0e38f;
                    if (c0 + 1 > R0)     sc[nt][1] = -3.0e38f;
                    if (c0     > R0 + 8) sc[nt][2] = -3.0e38f;
                    if (c0 + 1 > R0 + 8) sc[nt][3] = -3.0e38f;
                }
            }

            float tm0 = -3.0e38f, tm1 = -3.0e38f;
#pragma unroll
            for (int nt = 0; nt < 8; nt++) {
                tm0 = fmaxf(tm0, fmaxf(sc[nt][0], sc[nt][1]));
                tm1 = fmaxf(tm1, fmaxf(sc[nt][2], sc[nt][3]));
            }
            tm0 = fmaxf(tm0, __shfl_xor_sync(0xffffffffu, tm0, 1));
            tm0 = fmaxf(tm0, __shfl_xor_sync(0xffffffffu, tm0, 2));
            tm1 = fmaxf(tm1, __shfl_xor_sync(0xffffffffu, tm1, 1));
            tm1 = fmaxf(tm1, __shfl_xor_sync(0xffffffffu, tm1, 2));
            float mn0 = fmaxf(m0, tm0), mn1 = fmaxf(m1, tm1);
            float c0 = __expf(m0 - mn0), c1 = __expf(m1 - mn1);

            float ps0 = 0.f, ps1 = 0.f;
            uint32_t phi[4][4], plo[4][4];
#pragma unroll
            for (int s = 0; s < 4; s++) {
#pragma unroll
                for (int h = 0; h < 2; h++) {
                    int nt = 2 * s + h;
                    float p0 = __expf(sc[nt][0] - mn0);
                    float p1 = __expf(sc[nt][1] - mn0);
                    float p2 = __expf(sc[nt][2] - mn1);
                    float p3 = __expf(sc[nt][3] - mn1);
                    ps0 += p0 + p1;
                    ps1 += p2 + p3;
                    split2(p0, p1, phi[s][2 * h],     plo[s][2 * h]);
                    split2(p2, p3, phi[s][2 * h + 1], plo[s][2 * h + 1]);
                }
            }
            ps0 += __shfl_xor_sync(0xffffffffu, ps0, 1);
            ps0 += __shfl_xor_sync(0xffffffffu, ps0, 2);
            ps1 += __shfl_xor_sync(0xffffffffu, ps1, 1);
            ps1 += __shfl_xor_sync(0xffffffffu, ps1, 2);
            ls0 = ls0 * c0 + ps0;
            ls1 = ls1 * c1 + ps1;
            m0 = mn0; m1 = mn1;

#pragma unroll
            for (int nt = 0; nt < 8; nt++) {
                o[nt][0] *= c0; o[nt][1] *= c0;
                o[nt][2] *= c1; o[nt][3] *= c1;
            }
#pragma unroll
            for (int nt = 0; nt < 8; nt++) {
                int row = (nt << 3) + brow;
                uint32_t rb = kvb + (uint32_t)row * 128u;
                uint32_t s0 = (uint32_t)((bu       ^ (row & 7)) << 4);
                uint32_t s1 = (uint32_t)(((4 + bu) ^ (row & 7)) << 4);
                uint32_t vh8[8], vl8[8];
                ldsm4(vh8,     rb + A_VHI + s0);
                ldsm4(vh8 + 4, rb + A_VHI + s1);
                ldsm4(vl8,     rb + A_VLO + s0);
                ldsm4(vl8 + 4, rb + A_VLO + s1);
#pragma unroll
                for (int s = 0; s < 4; s++) {
                    mma16816(o[nt], phi[s], vh8[2 * s], vh8[2 * s + 1]);
                    mma16816(o[nt], phi[s], vl8[2 * s], vl8[2 * s + 1]);
                    mma16816(o[nt], plo[s], vh8[2 * s], vh8[2 * s + 1]);
                }
            }
        }
        __syncthreads();
    }

    const float inv0 = 1.f / ls0, inv1 = 1.f / ls1;
    const int R0g = q0 + (w << 4) + (l >> 2);
    float* o0p = out + (((size_t)(b * Tn + R0g)) << 6) + ((l & 3) << 1);
    float* o1p = o0p + (8 << 6);
#pragma unroll
    for (int nt = 0; nt < 8; nt++) {
        *(float2*)(o0p + (nt << 3)) = make_float2(o[nt][0] * inv0, o[nt][1] * inv0);
        *(float2*)(o1p + (nt << 3)) = make_float2(o[nt][2] * inv1, o[nt][3] * inv1);
    }
}

// ===================== launch =====================
extern "C" void kernel_launch(void* const* d_in, const int* in_sizes, int n_in,
                              void* d_out, int out_size)
{
    const float* x  = (const float*)d_in[0];
    const float* WQ = (const float*)d_in[1];
    const float* WK = (const float*)d_in[2];
    const float* WV = (const float*)d_in[3];
    float* out = (float*)d_out;

    cudaFuncSetAttribute(proj_tc_kernel,
                         cudaFuncAttributeMaxDynamicSharedMemorySize, PROJ_SMEM);
    cudaFuncSetAttribute(attn_kernel,
                         cudaFuncAttributeMaxDynamicSharedMemorySize, ATTN_SMEM);

    prep_w<<<18, 256>>>(WQ, WK, WV);
    proj_tc_kernel<<<256, 256, PROJ_SMEM>>>(x);
    attn_kernel<<<512, 128, ATTN_SMEM>>>(out);
}

// round 8
// speedup vs baseline: 1.1034x; 1.0432x over previous
#include <cuda_runtime.h>
#include <cuda_bf16.h>
#include <cstdint>

#define Bn  16
#define Tn  2048
#define Cn  384
#define DKn 64

// Pre-split bf16 operands
__device__ __align__(16) __nv_bfloat16 g_qhi [Bn * Tn * DKn];
__device__ __align__(16) __nv_bfloat16 g_qlo [Bn * Tn * DKn];
__device__ __align__(16) __nv_bfloat16 g_khi [Bn * Tn * DKn];
__device__ __align__(16) __nv_bfloat16 g_klo [Bn * Tn * DKn];
__device__ __align__(16) __nv_bfloat16 g_vthi[Bn * DKn * Tn];   // [b][d][t]
__device__ __align__(16) __nv_bfloat16 g_vtlo[Bn * DKn * Tn];
// Pre-transposed, pre-split weights: [n][k] with n in 0..191 = [Q|K|V]
__device__ __align__(16) __nv_bfloat16 g_wthi[192 * Cn];
__device__ __align__(16) __nv_bfloat16 g_wtlo[192 * Cn];

// ===================== helpers =====================
__device__ __forceinline__ uint32_t smem_u32(const void* p) {
    uint32_t a;
    asm("{ .reg .u64 t; cvta.to.shared.u64 t, %1; cvt.u32.u64 %0, t; }" : "=r"(a) : "l"(p));
    return a;
}
__device__ __forceinline__ uint32_t pack2(float e0, float e1) {
    uint32_t r;
    asm("cvt.rn.bf16x2.f32 %0, %1, %2;" : "=r"(r) : "f"(e1), "f"(e0));
    return r;
}
__device__ __forceinline__ void split2(float e0, float e1, uint32_t& hi, uint32_t& lo) {
    hi = pack2(e0, e1);
    float h0 = __uint_as_float(hi << 16);
    float h1 = __uint_as_float(hi & 0xffff0000u);
    lo = pack2(e0 - h0, e1 - h1);
}
__device__ __forceinline__ void ldsm4(uint32_t r[4], uint32_t addr) {
    asm volatile("ldmatrix.sync.aligned.m8n8.x4.shared.b16 {%0,%1,%2,%3}, [%4];"
        : "=r"(r[0]), "=r"(r[1]), "=r"(r[2]), "=r"(r[3]) : "r"(addr));
}
__device__ __forceinline__ void mma16816(float c[4], const uint32_t a[4],
                                         uint32_t b0, uint32_t b1) {
    asm volatile(
        "mma.sync.aligned.m16n8k16.row.col.f32.bf16.bf16.f32 "
        "{%0,%1,%2,%3},{%4,%5,%6,%7},{%8,%9},{%0,%1,%2,%3};"
        : "+f"(c[0]), "+f"(c[1]), "+f"(c[2]), "+f"(c[3])
        : "r"(a[0]), "r"(a[1]), "r"(a[2]), "r"(a[3]), "r"(b0), "r"(b1));
}
#define STS128(a, v) \
    asm volatile("st.shared.v4.b32 [%0], {%1,%2,%3,%4};" \
        :: "r"(a), "r"((v).x), "r"((v).y), "r"((v).z), "r"((v).w) : "memory")
#define CP16(sm, gp) \
    asm volatile("cp.async.cg.shared.global [%0], [%1], 16;" :: "r"(sm), "l"(gp) : "memory")
#define CP_COMMIT() asm volatile("cp.async.commit_group;" ::: "memory")
#define CP_WAIT(n)  asm volatile("cp.async.wait_group %0;" :: "n"(n) : "memory")

extern __shared__ __align__(16) char dsmem[];

// ===================== prep_w: transpose + split W once (coalesced) =========
__global__ __launch_bounds__(256) void prep_w(
    const float* __restrict__ WQ,
    const float* __restrict__ WK,
    const float* __restrict__ WV)
{
    __shared__ float sw[64][65];
    const int tid = threadIdx.x;
    const int m   = blockIdx.x / 6;
    const int kk  = (blockIdx.x % 6) * 64;
    const float* W = (m == 0) ? WQ : ((m == 1) ? WK : WV);

#pragma unroll
    for (int it = 0; it < 4; it++) {
        int idx = tid + (it << 8);
        int k = idx >> 4, n4 = (idx & 15) << 2;
        float4 v = *(const float4*)(W + (size_t)(kk + k) * DKn + n4);
        sw[k][n4] = v.x; sw[k][n4 + 1] = v.y; sw[k][n4 + 2] = v.z; sw[k][n4 + 3] = v.w;
    }
    __syncthreads();

#pragma unroll
    for (int it = 0; it < 2; it++) {
        int idx = tid + (it << 8);
        int n = idx >> 3, k0 = (idx & 7) << 3;
        uint32_t h[4], lo[4];
#pragma unroll
        for (int j = 0; j < 4; j++)
            split2(sw[k0 + 2 * j][n], sw[k0 + 2 * j + 1][n], h[j], lo[j]);
        size_t off = (size_t)(m * 64 + n) * Cn + kk + k0;
        *(uint4*)(g_wthi + off) = make_uint4(h[0], h[1], h[2], h[3]);
        *(uint4*)(g_wtlo + off) = make_uint4(lo[0], lo[1], lo[2], lo[3]);
    }
}

// ===================== projection: fully async staging =====================
// smem: X fp32 double buffer @0 (each 128 rows x 288B = 36864B);
//       WT double buffer @73728 (each 48KB: hi +0, lo +24576).
#define P_X0 0u
#define P_XSTRIDE 36864u
#define P_WT0 73728u
#define P_WSTRIDE 49152u
#define PROJ_SMEM (172032u + 128u)

__device__ __forceinline__ void stage_wt_async(uint32_t dst, int kk, int tid) {
#pragma unroll
    for (int i = 0; i < 6; i++) {
        int idx = tid + (i << 8);
        int n = idx >> 3, u = idx & 7;
        uint32_t sw = (uint32_t)n * 128u + (uint32_t)((u ^ (n & 7)) << 4);
        CP16(dst + sw,          g_wthi + n * Cn + kk + (u << 3));
        CP16(dst + 24576u + sw, g_wtlo + n * Cn + kk + (u << 3));
    }
}
__device__ __forceinline__ void stage_x_async(uint32_t dst, const float* xp, int tid) {
    // xp points at x[r0][kk]; 128 rows x 64 floats, row stride 288B in smem
#pragma unroll
    for (int i = 0; i < 8; i++) {
        int idx = tid + (i << 8);             // < 2048
        int r = idx >> 4, u = idx & 15;
        CP16(dst + (uint32_t)r * 288u + (uint32_t)(u << 4),
             xp + (size_t)r * Cn + (u << 2));
    }
}

__global__ __launch_bounds__(256, 1) void proj_tc_kernel(const float* __restrict__ x)
{
    uint32_t raw = smem_u32(dsmem);
    uint32_t sb  = (raw + 127u) & ~127u;
    char*    bp  = dsmem + (sb - raw);
    float (*vt)[65] = (float(*)[65])(bp + P_WT0);   // epilogue overlay

    const int tid = threadIdx.x;
    const int w   = tid >> 5;
    const int l   = tid & 31;
    const int r0  = blockIdx.x * 128;

    float acc[24][4];
#pragma unroll
    for (int i = 0; i < 24; i++)
#pragma unroll
        for (int j = 0; j < 4; j++) acc[i][j] = 0.f;

    const int brow = l & 7;
    const int bu   = l >> 3;
    const int ra   = (w << 4) + (l >> 2);     // A-fragment row (0..127)

    stage_x_async(sb + P_X0, x + (size_t)r0 * Cn, tid);
    stage_wt_async(sb + P_WT0, 0, tid);
    CP_COMMIT();

    for (int c = 0; c < Cn / 64; c++) {
        if (c + 1 < Cn / 64) {
            stage_x_async(sb + P_X0 + (uint32_t)((c + 1) & 1) * P_XSTRIDE,
                          x + (size_t)r0 * Cn + (c + 1) * 64, tid);
            stage_wt_async(sb + P_WT0 + (uint32_t)((c + 1) & 1) * P_WSTRIDE,
                           (c + 1) * 64, tid);
            CP_COMMIT();
            CP_WAIT(1);
        } else {
            CP_WAIT(0);
        }
        __syncthreads();

        const char*    xb  = bp + P_X0 + (uint32_t)(c & 1) * P_XSTRIDE;
        const uint32_t wtb = sb + P_WT0 + (uint32_t)(c & 1) * P_WSTRIDE;

        // ---- A fragments: fp32 LDS in fragment layout + register split ----
        uint32_t ah[4][4], al[4][4];
        {
            const char* rowa = xb + (uint32_t)ra * 288u;
            const char* rowb = rowa + 8u * 288u;
#pragma unroll
            for (int ks = 0; ks < 4; ks++) {
                int c0 = (ks << 6) + ((l & 3) << 3);        // byte offset of col0
                float2 p0 = *(const float2*)(rowa + c0);
                float2 p1 = *(const float2*)(rowb + c0);
                float2 p2 = *(const float2*)(rowa + c0 + 32);
                float2 p3 = *(const float2*)(rowb + c0 + 32);
                split2(p0.x, p0.y, ah[ks][0], al[ks][0]);
                split2(p1.x, p1.y, ah[ks][1], al[ks][1]);
                split2(p2.x, p2.y, ah[ks][2], al[ks][2]);
                split2(p3.x, p3.y, ah[ks][3], al[ks][3]);
            }
        }
#pragma unroll
        for (int nt = 0; nt < 24; nt++) {
            int rowb = (nt << 3) + brow;
            uint32_t rb = wtb + (uint32_t)rowb * 128u;
            uint32_t s0 = (uint32_t)((bu       ^ (rowb & 7)) << 4);
            uint32_t s1 = (uint32_t)(((4 + bu) ^ (rowb & 7)) << 4);
            uint32_t bh[8], bl[8];
            ldsm4(bh,     rb + s0);
            ldsm4(bh + 4, rb + s1);
            ldsm4(bl,     rb + 24576u + s0);
            ldsm4(bl + 4, rb + 24576u + s1);
#pragma unroll
            for (int s = 0; s < 4; s++) {
                mma16816(acc[nt], ah[s], bh[2 * s], bh[2 * s + 1]);
                mma16816(acc[nt], ah[s], bl[2 * s], bl[2 * s + 1]);
                mma16816(acc[nt], al[s], bh[2 * s], bh[2 * s + 1]);
            }
        }
        __syncthreads();
    }

    // ---- epilogue: Q (x0.125) / K split-store; V staged for transpose ----
    const int rl = (w << 4) + (l >> 2);
    const int cc = (l & 3) << 1;
    const size_t row0 = (size_t)(r0 + rl);
#pragma unroll
    for (int nt = 0; nt < 8; nt++) {
        int cidx = (nt << 3) + cc;
        uint32_t h, lo;
        split2(acc[nt][0] * 0.125f, acc[nt][1] * 0.125f, h, lo);
        *(uint32_t*)(g_qhi + row0 * 64 + cidx) = h;
        *(uint32_t*)(g_qlo + row0 * 64 + cidx) = lo;
        split2(acc[nt][2] * 0.125f, acc[nt][3] * 0.125f, h, lo);
        *(uint32_t*)(g_qhi + (row0 + 8) * 64 + cidx) = h;
        *(uint32_t*)(g_qlo + (row0 + 8) * 64 + cidx) = lo;

        split2(acc[nt + 8][0], acc[nt + 8][1], h, lo);
        *(uint32_t*)(g_khi + row0 * 64 + cidx) = h;
        *(uint32_t*)(g_klo + row0 * 64 + cidx) = lo;
        split2(acc[nt + 8][2], acc[nt + 8][3], h, lo);
        *(uint32_t*)(g_khi + (row0 + 8) * 64 + cidx) = h;
        *(uint32_t*)(g_klo + (row0 + 8) * 64 + cidx) = lo;

        vt[rl][cidx]         = acc[nt + 16][0];
        vt[rl][cidx + 1]     = acc[nt + 16][1];
        vt[rl + 8][cidx]     = acc[nt + 16][2];
        vt[rl + 8][cidx + 1] = acc[nt + 16][3];
    }
    __syncthreads();

    {
        const int b  = r0 >> 11;
        const int t0 = r0 & 2047;
        const int d  = tid >> 2;
        const int tq = (tid & 3) << 5;
#pragma unroll
        for (int g = 0; g < 8; g++) {
            int tl = tq + g * 4;
            float v0 = vt[tl][d], v1 = vt[tl + 1][d];
            float v2 = vt[tl + 2][d], v3 = vt[tl + 3][d];
            uint32_t h0, h1, l0, l1;
            split2(v0, v1, h0, l0);
            split2(v2, v3, h1, l1);
            size_t off = ((size_t)(b * DKn + d) << 11) + t0 + tl;
            *(uint2*)(g_vthi + off) = make_uint2(h0, h1);
            *(uint2*)(g_vtlo + off) = make_uint2(l0, l1);
        }
    }
}

// ===================== attention (128 threads, 64-row q-tiles, 2 CTAs/SM) ===
#define A_QHI 0u
#define A_QLO 8192u
#define A_KV0 16384u
#define A_KHI 0u
#define A_KLO 8192u
#define A_VHI 16384u
#define A_VLO 24576u
#define ATTN_SMEM (81920u + 128u)

__device__ __forceinline__ void stage_kv_async(uint32_t dst, int b, int ks, int tid) {
    const __nv_bfloat16* kh = g_khi + (((size_t)(b * Tn + ks)) << 6);
    const __nv_bfloat16* kl = g_klo + (((size_t)(b * Tn + ks)) << 6);
    const __nv_bfloat16* vh = g_vthi + (((size_t)(b * DKn)) << 11) + ks;
    const __nv_bfloat16* vl = g_vtlo + (((size_t)(b * DKn)) << 11) + ks;
#pragma unroll
    for (int i = 0; i < 4; i++) {
        int idx = tid + (i << 7);
        int r = idx >> 3, u = idx & 7;
        uint32_t sw = (uint32_t)r * 128u + (uint32_t)((u ^ (r & 7)) << 4);
        CP16(dst + A_KHI + sw, kh + (r << 6) + (u << 3));
        CP16(dst + A_KLO + sw, kl + (r << 6) + (u << 3));
        CP16(dst + A_VHI + sw, vh + ((size_t)r << 11) + (u << 3));
        CP16(dst + A_VLO + sw, vl + ((size_t)r << 11) + (u << 3));
    }
}

__global__ __launch_bounds__(128, 2) void attn_kernel(float* __restrict__ out)
{
    uint32_t raw = smem_u32(dsmem);
    uint32_t sb  = (raw + 127u) & ~127u;

    const int tid = threadIdx.x;
    const int w   = tid >> 5;
    const int l   = tid & 31;

    const int bx = blockIdx.x;
    const int qt = 31 - (bx >> 4);
    const int b  = bx & 15;
    const int q0 = qt << 6;

    stage_kv_async(sb + A_KV0, b, 0, tid);
    CP_COMMIT();

    {
        const uint4* qh = (const uint4*)(g_qhi + (((size_t)(b * Tn + q0)) << 6));
        const uint4* ql = (const uint4*)(g_qlo + (((size_t)(b * Tn + q0)) << 6));
#pragma unroll
        for (int i = 0; i < 4; i++) {
            int idx = tid + (i << 7);
            int r = idx >> 3, u = idx & 7;
            uint32_t sw = (uint32_t)r * 128u + (uint32_t)((u ^ (r & 7)) << 4);
            uint4 vh = qh[idx], vl = ql[idx];
            STS128(sb + A_QHI + sw, vh);
            STS128(sb + A_QLO + sw, vl);
        }
    }
    __syncthreads();

    uint32_t qh[4][4], qlr[4][4];
    {
        int arow = (w << 4) + (l & 7) + (((l >> 3) & 1) << 3);
        uint32_t rb = sb + (uint32_t)arow * 128u;
#pragma unroll
        for (int kk = 0; kk < 4; kk++) {
            int u = (kk << 1) + (l >> 4);
            uint32_t sw = (uint32_t)((u ^ (arow & 7)) << 4);
            ldsm4(qh[kk],  rb + A_QHI + sw);
            ldsm4(qlr[kk], rb + A_QLO + sw);
        }
    }

    float m0 = -3.0e38f, m1 = -3.0e38f, ls0 = 0.f, ls1 = 0.f;
    float o[8][4];
#pragma unroll
    for (int i = 0; i < 8; i++)
#pragma unroll
        for (int j = 0; j < 4; j++) o[i][j] = 0.f;

    const int kend  = q0 + 64;
    const int wrow0 = q0 + (w << 4);
    const int brow  = l & 7;
    const int bu    = l >> 3;

    int it = 0;
    for (int ks = 0; ks < kend; ks += 64, it++) {
        if (ks + 64 < kend) {
            stage_kv_async(sb + A_KV0 + (uint32_t)((it + 1) & 1) * 32768u,
                           b, ks + 64, tid);
            CP_COMMIT();
            CP_WAIT(1);
        } else {
            CP_WAIT(0);
        }
        __syncthreads();

        const uint32_t kvb = sb + A_KV0 + (uint32_t)(it & 1) * 32768u;

        if (ks <= wrow0 + 15) {
            float sc[8][4];
#pragma unroll
            for (int nt = 0; nt < 8; nt++) {
                int row = (nt << 3) + brow;
                uint32_t rb = kvb + (uint32_t)row * 128u;
                uint32_t s0 = (uint32_t)((bu       ^ (row & 7)) << 4);
                uint32_t s1 = (uint32_t)(((4 + bu) ^ (row & 7)) << 4);
                uint32_t kh8[8], kl8[8];
                ldsm4(kh8,     rb + A_KHI + s0);
                ldsm4(kh8 + 4, rb + A_KHI + s1);
                ldsm4(kl8,     rb + A_KLO + s0);
                ldsm4(kl8 + 4, rb + A_KLO + s1);
#pragma unroll
                for (int j = 0; j < 4; j++) sc[nt][j] = 0.f;
#pragma unroll
                for (int s = 0; s < 4; s++) {
                    mma16816(sc[nt], qh[s],  kh8[2 * s], kh8[2 * s + 1]);
                    mma16816(sc[nt], qh[s],  kl8[2 * s], kl8[2 * s + 1]);
                    mma16816(sc[nt], qlr[s], kh8[2 * s], kh8[2 * s + 1]);
                }
            }

            const int R0 = wrow0 + (l >> 2);
            if (ks + 64 > wrow0) {
                int colb = ks + ((l & 3) << 1);
#pragma unroll
                for (int nt = 0; nt < 8; nt++) {
                    int c0 = colb + (nt << 3);
                    if (c0     > R0)     sc[nt][0] = -3.0e38f;
                    if (c0 + 1 > R0)     sc[nt][1] = -3.0e38f;
                    if (c0     > R0 + 8) sc[nt][2] = -3.0e38f;
                    if (c0 + 1 > R0 + 8) sc[nt][3] = -3.0e38f;
                }
            }

            float tm0 = -3.0e38f, tm1 = -3.0e38f;
#pragma unroll
            for (int nt = 0; nt < 8; nt++) {
                tm0 = fmaxf(tm0, fmaxf(sc[nt][0], sc[nt][1]));
                tm1 = fmaxf(tm1, fmaxf(sc[nt][2], sc[nt][3]));
            }
            tm0 = fmaxf(tm0, __shfl_xor_sync(0xffffffffu, tm0, 1));
            tm0 = fmaxf(tm0, __shfl_xor_sync(0xffffffffu, tm0, 2));
            tm1 = fmaxf(tm1, __shfl_xor_sync(0xffffffffu, tm1, 1));
            tm1 = fmaxf(tm1, __shfl_xor_sync(0xffffffffu, tm1, 2));
            float mn0 = fmaxf(m0, tm0), mn1 = fmaxf(m1, tm1);
            float c0 = __expf(m0 - mn0), c1 = __expf(m1 - mn1);

            float ps0 = 0.f, ps1 = 0.f;
            uint32_t phi[4][4], plo[4][4];
#pragma unroll
            for (int s = 0; s < 4; s++) {
#pragma unroll
                for (int h = 0; h < 2; h++) {
                    int nt = 2 * s + h;
                    float p0 = __expf(sc[nt][0] - mn0);
                    float p1 = __expf(sc[nt][1] - mn0);
                    float p2 = __expf(sc[nt][2] - mn1);
                    float p3 = __expf(sc[nt][3] - mn1);
                    ps0 += p0 + p1;
                    ps1 += p2 + p3;
                    split2(p0, p1, phi[s][2 * h],     plo[s][2 * h]);
                    split2(p2, p3, phi[s][2 * h + 1], plo[s][2 * h + 1]);
                }
            }
            ps0 += __shfl_xor_sync(0xffffffffu, ps0, 1);
            ps0 += __shfl_xor_sync(0xffffffffu, ps0, 2);
            ps1 += __shfl_xor_sync(0xffffffffu, ps1, 1);
            ps1 += __shfl_xor_sync(0xffffffffu, ps1, 2);
            ls0 = ls0 * c0 + ps0;
            ls1 = ls1 * c1 + ps1;
            m0 = mn0; m1 = mn1;

#pragma unroll
            for (int nt = 0; nt < 8; nt++) {
                o[nt][0] *= c0; o[nt][1] *= c0;
                o[nt][2] *= c1; o[nt][3] *= c1;
            }
#pragma unroll
            for (int nt = 0; nt < 8; nt++) {
                int row = (nt << 3) + brow;
                uint32_t rb = kvb + (uint32_t)row * 128u;
                uint32_t s0 = (uint32_t)((bu       ^ (row & 7)) << 4);
                uint32_t s1 = (uint32_t)(((4 + bu) ^ (row & 7)) << 4);
                uint32_t vh8[8], vl8[8];
                ldsm4(vh8,     rb + A_VHI + s0);
                ldsm4(vh8 + 4, rb + A_VHI + s1);
                ldsm4(vl8,     rb + A_VLO + s0);
                ldsm4(vl8 + 4, rb + A_VLO + s1);
#pragma unroll
                for (int s = 0; s < 4; s++) {
                    mma16816(o[nt], phi[s], vh8[2 * s], vh8[2 * s + 1]);
                    mma16816(o[nt], phi[s], vl8[2 * s], vl8[2 * s + 1]);
                    mma16816(o[nt], plo[s], vh8[2 * s], vh8[2 * s + 1]);
                }
            }
        }
        __syncthreads();
    }

    const float inv0 = 1.f / ls0, inv1 = 1.f / ls1;
    const int R0g = q0 + (w << 4) + (l >> 2);
    float* o0p = out + (((size_t)(b * Tn + R0g)) << 6) + ((l & 3) << 1);
    float* o1p = o0p + (8 << 6);
#pragma unroll
    for (int nt = 0; nt < 8; nt++) {
        *(float2*)(o0p + (nt << 3)) = make_float2(o[nt][0] * inv0, o[nt][1] * inv0);
        *(float2*)(o1p + (nt << 3)) = make_float2(o[nt][2] * inv1, o[nt][3] * inv1);
    }
}

// ===================== launch =====================
extern "C" void kernel_launch(void* const* d_in, const int* in_sizes, int n_in,
                              void* d_out, int out_size)
{
    const float* x  = (const float*)d_in[0];
    const float* WQ = (const float*)d_in[1];
    const float* WK = (const float*)d_in[2];
    const float* WV = (const float*)d_in[3];
    float* out = (float*)d_out;

    cudaFuncSetAttribute(proj_tc_kernel,
                         cudaFuncAttributeMaxDynamicSharedMemorySize, PROJ_SMEM);
    cudaFuncSetAttribute(attn_kernel,
                         cudaFuncAttributeMaxDynamicSharedMemorySize, ATTN_SMEM);

    prep_w<<<18, 256>>>(WQ, WK, WV);
    proj_tc_kernel<<<256, 256, PROJ_SMEM>>>(x);
    attn_kernel<<<512, 128, ATTN_SMEM>>>(out);
}

// round 9
// speedup vs baseline: 1.1118x; 1.0076x over previous
#include <cuda_runtime.h>
#include <cuda_bf16.h>
#include <cstdint>

#define Bn  16
#define Tn  2048
#define Cn  384
#define DKn 64

// Pre-split bf16 operands
__device__ __align__(16) __nv_bfloat16 g_qhi [Bn * Tn * DKn];
__device__ __align__(16) __nv_bfloat16 g_qlo [Bn * Tn * DKn];
__device__ __align__(16) __nv_bfloat16 g_khi [Bn * Tn * DKn];
__device__ __align__(16) __nv_bfloat16 g_klo [Bn * Tn * DKn];
__device__ __align__(16) __nv_bfloat16 g_vthi[Bn * DKn * Tn];   // [b][d][t]
__device__ __align__(16) __nv_bfloat16 g_vtlo[Bn * DKn * Tn];
// Pre-transposed, pre-split weights: [n][k] with n in 0..191 = [Q|K|V]
__device__ __align__(16) __nv_bfloat16 g_wthi[192 * Cn];
__device__ __align__(16) __nv_bfloat16 g_wtlo[192 * Cn];

// ===================== helpers =====================
__device__ __forceinline__ uint32_t smem_u32(const void* p) {
    uint32_t a;
    asm("{ .reg .u64 t; cvta.to.shared.u64 t, %1; cvt.u32.u64 %0, t; }" : "=r"(a) : "l"(p));
    return a;
}
__device__ __forceinline__ uint32_t pack2(float e0, float e1) {
    uint32_t r;
    asm("cvt.rn.bf16x2.f32 %0, %1, %2;" : "=r"(r) : "f"(e1), "f"(e0));
    return r;
}
__device__ __forceinline__ void split2(float e0, float e1, uint32_t& hi, uint32_t& lo) {
    hi = pack2(e0, e1);
    float h0 = __uint_as_float(hi << 16);
    float h1 = __uint_as_float(hi & 0xffff0000u);
    lo = pack2(e0 - h0, e1 - h1);
}
__device__ __forceinline__ void ldsm4(uint32_t r[4], uint32_t addr) {
    asm volatile("ldmatrix.sync.aligned.m8n8.x4.shared.b16 {%0,%1,%2,%3}, [%4];"
        : "=r"(r[0]), "=r"(r[1]), "=r"(r[2]), "=r"(r[3]) : "r"(addr));
}
__device__ __forceinline__ void mma16816(float c[4], const uint32_t a[4],
                                         uint32_t b0, uint32_t b1) {
    asm volatile(
        "mma.sync.aligned.m16n8k16.row.col.f32.bf16.bf16.f32 "
        "{%0,%1,%2,%3},{%4,%5,%6,%7},{%8,%9},{%0,%1,%2,%3};"
        : "+f"(c[0]), "+f"(c[1]), "+f"(c[2]), "+f"(c[3])
        : "r"(a[0]), "r"(a[1]), "r"(a[2]), "r"(a[3]), "r"(b0), "r"(b1));
}
#define STS128(a, v) \
    asm volatile("st.shared.v4.b32 [%0], {%1,%2,%3,%4};" \
        :: "r"(a), "r"((v).x), "r"((v).y), "r"((v).z), "r"((v).w) : "memory")
#define CP16(sm, gp) \
    asm volatile("cp.async.cg.shared.global [%0], [%1], 16;" :: "r"(sm), "l"(gp) : "memory")
#define CP_COMMIT() asm volatile("cp.async.commit_group;" ::: "memory")
#define CP_WAIT(n)  asm volatile("cp.async.wait_group %0;" :: "n"(n) : "memory")

extern __shared__ __align__(16) char dsmem[];

// ===================== prep_w: transpose + split W once (coalesced) =========
__global__ __launch_bounds__(256) void prep_w(
    const float* __restrict__ WQ,
    const float* __restrict__ WK,
    const float* __restrict__ WV)
{
    __shared__ float sw[64][65];
    const int tid = threadIdx.x;
    const int m   = blockIdx.x / 6;
    const int kk  = (blockIdx.x % 6) * 64;
    const float* W = (m == 0) ? WQ : ((m == 1) ? WK : WV);

#pragma unroll
    for (int it = 0; it < 4; it++) {
        int idx = tid + (it << 8);
        int k = idx >> 4, n4 = (idx & 15) << 2;
        float4 v = *(const float4*)(W + (size_t)(kk + k) * DKn + n4);
        sw[k][n4] = v.x; sw[k][n4 + 1] = v.y; sw[k][n4 + 2] = v.z; sw[k][n4 + 3] = v.w;
    }
    __syncthreads();

#pragma unroll
    for (int it = 0; it < 2; it++) {
        int idx = tid + (it << 8);
        int n = idx >> 3, k0 = (idx & 7) << 3;
        uint32_t h[4], lo[4];
#pragma unroll
        for (int j = 0; j < 4; j++)
            split2(sw[k0 + 2 * j][n], sw[k0 + 2 * j + 1][n], h[j], lo[j]);
        size_t off = (size_t)(m * 64 + n) * Cn + kk + k0;
        *(uint4*)(g_wthi + off) = make_uint4(h[0], h[1], h[2], h[3]);
        *(uint4*)(g_wtlo + off) = make_uint4(lo[0], lo[1], lo[2], lo[3]);
    }
}

// ===================== projection: fully async staging =====================
// smem: X fp32 double buffer @0 (each 128 rows x 288B = 36864B);
//       WT double buffer @73728 (each 48KB: hi +0, lo +24576).
#define P_X0 0u
#define P_XSTRIDE 36864u
#define P_WT0 73728u
#define P_WSTRIDE 49152u
#define PROJ_SMEM (172032u + 128u)

__device__ __forceinline__ void stage_wt_async(uint32_t dst, int kk, int tid) {
#pragma unroll
    for (int i = 0; i < 6; i++) {
        int idx = tid + (i << 8);
        int n = idx >> 3, u = idx & 7;
        uint32_t sw = (uint32_t)n * 128u + (uint32_t)((u ^ (n & 7)) << 4);
        CP16(dst + sw,          g_wthi + n * Cn + kk + (u << 3));
        CP16(dst + 24576u + sw, g_wtlo + n * Cn + kk + (u << 3));
    }
}
__device__ __forceinline__ void stage_x_async(uint32_t dst, const float* xp, int tid) {
#pragma unroll
    for (int i = 0; i < 8; i++) {
        int idx = tid + (i << 8);
        int r = idx >> 4, u = idx & 15;
        CP16(dst + (uint32_t)r * 288u + (uint32_t)(u << 4),
             xp + (size_t)r * Cn + (u << 2));
    }
}

__global__ __launch_bounds__(256, 1) void proj_tc_kernel(const float* __restrict__ x)
{
    uint32_t raw = smem_u32(dsmem);
    uint32_t sb  = (raw + 127u) & ~127u;
    char*    bp  = dsmem + (sb - raw);
    float (*vt)[65] = (float(*)[65])(bp + P_WT0);

    const int tid = threadIdx.x;
    const int w   = tid >> 5;
    const int l   = tid & 31;
    const int r0  = blockIdx.x * 128;

    float acc[24][4];
#pragma unroll
    for (int i = 0; i < 24; i++)
#pragma unroll
        for (int j = 0; j < 4; j++) acc[i][j] = 0.f;

    const int brow = l & 7;
    const int bu   = l >> 3;
    const int ra   = (w << 4) + (l >> 2);

    stage_x_async(sb + P_X0, x + (size_t)r0 * Cn, tid);
    stage_wt_async(sb + P_WT0, 0, tid);
    CP_COMMIT();

    for (int c = 0; c < Cn / 64; c++) {
        if (c + 1 < Cn / 64) {
            stage_x_async(sb + P_X0 + (uint32_t)((c + 1) & 1) * P_XSTRIDE,
                          x + (size_t)r0 * Cn + (c + 1) * 64, tid);
            stage_wt_async(sb + P_WT0 + (uint32_t)((c + 1) & 1) * P_WSTRIDE,
                           (c + 1) * 64, tid);
            CP_COMMIT();
            CP_WAIT(1);
        } else {
            CP_WAIT(0);
        }
        __syncthreads();

        const char*    xb  = bp + P_X0 + (uint32_t)(c & 1) * P_XSTRIDE;
        const uint32_t wtb = sb + P_WT0 + (uint32_t)(c & 1) * P_WSTRIDE;

        uint32_t ah[4][4], al[4][4];
        {
            const char* rowa = xb + (uint32_t)ra * 288u;
            const char* rowb = rowa + 8u * 288u;
#pragma unroll
            for (int ks = 0; ks < 4; ks++) {
                int c0 = (ks << 6) + ((l & 3) << 3);
                float2 p0 = *(const float2*)(rowa + c0);
                float2 p1 = *(const float2*)(rowb + c0);
                float2 p2 = *(const float2*)(rowa + c0 + 32);
                float2 p3 = *(const float2*)(rowb + c0 + 32);
                split2(p0.x, p0.y, ah[ks][0], al[ks][0]);
                split2(p1.x, p1.y, ah[ks][1], al[ks][1]);
                split2(p2.x, p2.y, ah[ks][2], al[ks][2]);
                split2(p3.x, p3.y, ah[ks][3], al[ks][3]);
            }
        }
#pragma unroll
        for (int nt = 0; nt < 24; nt++) {
            int rowb = (nt << 3) + brow;
            uint32_t rb = wtb + (uint32_t)rowb * 128u;
            uint32_t s0 = (uint32_t)((bu       ^ (rowb & 7)) << 4);
            uint32_t s1 = (uint32_t)(((4 + bu) ^ (rowb & 7)) << 4);
            uint32_t bh[8], bl[8];
            ldsm4(bh,     rb + s0);
            ldsm4(bh + 4, rb + s1);
            ldsm4(bl,     rb + 24576u + s0);
            ldsm4(bl + 4, rb + 24576u + s1);
#pragma unroll
            for (int s = 0; s < 4; s++) {
                mma16816(acc[nt], ah[s], bh[2 * s], bh[2 * s + 1]);
                mma16816(acc[nt], ah[s], bl[2 * s], bl[2 * s + 1]);
                mma16816(acc[nt], al[s], bh[2 * s], bh[2 * s + 1]);
            }
        }
        __syncthreads();
    }

    // ---- epilogue: Q (x0.125) / K split-store; V staged for transpose ----
    const int rl = (w << 4) + (l >> 2);
    const int cc = (l & 3) << 1;
    const size_t row0 = (size_t)(r0 + rl);
#pragma unroll
    for (int nt = 0; nt < 8; nt++) {
        int cidx = (nt << 3) + cc;
        uint32_t h, lo;
        split2(acc[nt][0] * 0.125f, acc[nt][1] * 0.125f, h, lo);
        *(uint32_t*)(g_qhi + row0 * 64 + cidx) = h;
        *(uint32_t*)(g_qlo + row0 * 64 + cidx) = lo;
        split2(acc[nt][2] * 0.125f, acc[nt][3] * 0.125f, h, lo);
        *(uint32_t*)(g_qhi + (row0 + 8) * 64 + cidx) = h;
        *(uint32_t*)(g_qlo + (row0 + 8) * 64 + cidx) = lo;

        split2(acc[nt + 8][0], acc[nt + 8][1], h, lo);
        *(uint32_t*)(g_khi + row0 * 64 + cidx) = h;
        *(uint32_t*)(g_klo + row0 * 64 + cidx) = lo;
        split2(acc[nt + 8][2], acc[nt + 8][3], h, lo);
        *(uint32_t*)(g_khi + (row0 + 8) * 64 + cidx) = h;
        *(uint32_t*)(g_klo + (row0 + 8) * 64 + cidx) = lo;

        vt[rl][cidx]         = acc[nt + 16][0];
        vt[rl][cidx + 1]     = acc[nt + 16][1];
        vt[rl + 8][cidx]     = acc[nt + 16][2];
        vt[rl + 8][cidx + 1] = acc[nt + 16][3];
    }
    __syncthreads();

    {
        const int b  = r0 >> 11;
        const int t0 = r0 & 2047;
        const int d  = tid >> 2;
        const int tq = (tid & 3) << 5;
#pragma unroll
        for (int g = 0; g < 8; g++) {
            int tl = tq + g * 4;
            float v0 = vt[tl][d], v1 = vt[tl + 1][d];
            float v2 = vt[tl + 2][d], v3 = vt[tl + 3][d];
            uint32_t h0, h1, l0, l1;
            split2(v0, v1, h0, l0);
            split2(v2, v3, h1, l1);
            size_t off = ((size_t)(b * DKn + d) << 11) + t0 + tl;
            *(uint2*)(g_vthi + off) = make_uint2(h0, h1);
            *(uint2*)(g_vtlo + off) = make_uint2(l0, l1);
        }
    }
}

// ===================== attention: triple-buffered K/V, 1 sync/tile ==========
// smem: 3 KV buffers @0, each 32KB: KHI +0, KLO +8192, VHI +16384, VLO +24576.
#define A_KHI 0u
#define A_KLO 8192u
#define A_VHI 16384u
#define A_VLO 24576u
#define ATTN_SMEM (98304u + 128u)

__device__ __forceinline__ void stage_kv_async(uint32_t dst, int b, int ks, int tid) {
    const __nv_bfloat16* kh = g_khi + (((size_t)(b * Tn + ks)) << 6);
    const __nv_bfloat16* kl = g_klo + (((size_t)(b * Tn + ks)) << 6);
    const __nv_bfloat16* vh = g_vthi + (((size_t)(b * DKn)) << 11) + ks;
    const __nv_bfloat16* vl = g_vtlo + (((size_t)(b * DKn)) << 11) + ks;
#pragma unroll
    for (int i = 0; i < 4; i++) {
        int idx = tid + (i << 7);
        int r = idx >> 3, u = idx & 7;
        uint32_t sw = (uint32_t)r * 128u + (uint32_t)((u ^ (r & 7)) << 4);
        CP16(dst + A_KHI + sw, kh + (r << 6) + (u << 3));
        CP16(dst + A_KLO + sw, kl + (r << 6) + (u << 3));
        CP16(dst + A_VHI + sw, vh + ((size_t)r << 11) + (u << 3));
        CP16(dst + A_VLO + sw, vl + ((size_t)r << 11) + (u << 3));
    }
}

__global__ __launch_bounds__(128, 2) void attn_kernel(float* __restrict__ out)
{
    uint32_t raw = smem_u32(dsmem);
    uint32_t sb  = (raw + 127u) & ~127u;

    const int tid = threadIdx.x;
    const int w   = tid >> 5;
    const int l   = tid & 31;

    const int bx = blockIdx.x;
    const int qt = 31 - (bx >> 4);          // heavy q-tiles first
    const int b  = bx & 15;
    const int q0 = qt << 6;
    const int ntiles = qt + 1;

    // prefetch first two K/V tiles
    stage_kv_async(sb, b, 0, tid);
    CP_COMMIT();
    if (ntiles > 1) {
        stage_kv_async(sb + 32768u, b, 64, tid);
        CP_COMMIT();
    }

    // ---- Q fragments directly from global (canonical A-fragment layout) ----
    uint32_t qh[4][4], qlr[4][4];
    {
        const int rowa = q0 + (w << 4) + (l >> 2);
        const int cb   = (l & 3) << 1;
        const __nv_bfloat16* ph = g_qhi + (((size_t)(b * Tn + rowa)) << 6) + cb;
        const __nv_bfloat16* pl = g_qlo + (((size_t)(b * Tn + rowa)) << 6) + cb;
#pragma unroll
        for (int ks = 0; ks < 4; ks++) {
            int c0 = ks << 4;
            qh[ks][0]  = *(const uint32_t*)(ph + c0);
            qh[ks][1]  = *(const uint32_t*)(ph + 512 + c0);
            qh[ks][2]  = *(const uint32_t*)(ph + c0 + 8);
            qh[ks][3]  = *(const uint32_t*)(ph + 512 + c0 + 8);
            qlr[ks][0] = *(const uint32_t*)(pl + c0);
            qlr[ks][1] = *(const uint32_t*)(pl + 512 + c0);
            qlr[ks][2] = *(const uint32_t*)(pl + c0 + 8);
            qlr[ks][3] = *(const uint32_t*)(pl + 512 + c0 + 8);
        }
    }

    float m0 = -3.0e38f, m1 = -3.0e38f, ls0 = 0.f, ls1 = 0.f;
    float o[8][4];
#pragma unroll
    for (int i = 0; i < 8; i++)
#pragma unroll
        for (int j = 0; j < 4; j++) o[i][j] = 0.f;

    const int wrow0 = q0 + (w << 4);
    const int brow  = l & 7;
    const int bu    = l >> 3;

    int cslot = 0, pslot = 2;               // it%3 and (it+2)%3
    for (int it = 0; it < ntiles; it++) {
        const int ks = it << 6;
        if (it + 1 < ntiles) { CP_WAIT(1); } else { CP_WAIT(0); }
        __syncthreads();
        if (it + 2 < ntiles) {
            stage_kv_async(sb + (uint32_t)pslot * 32768u, b, ks + 128, tid);
            CP_COMMIT();
        }
        const uint32_t kvb = sb + (uint32_t)cslot * 32768u;
        cslot = (cslot == 2) ? 0 : cslot + 1;
        pslot = (pslot == 2) ? 0 : pslot + 1;

        if (ks <= wrow0 + 15) {
            float sc[8][4];
#pragma unroll
            for (int nt = 0; nt < 8; nt++) {
                int row = (nt << 3) + brow;
                uint32_t rb = kvb + (uint32_t)row * 128u;
                uint32_t s0 = (uint32_t)((bu       ^ (row & 7)) << 4);
                uint32_t s1 = (uint32_t)(((4 + bu) ^ (row & 7)) << 4);
                uint32_t kh8[8], kl8[8];
                ldsm4(kh8,     rb + A_KHI + s0);
                ldsm4(kh8 + 4, rb + A_KHI + s1);
                ldsm4(kl8,     rb + A_KLO + s0);
                ldsm4(kl8 + 4, rb + A_KLO + s1);
#pragma unroll
                for (int j = 0; j < 4; j++) sc[nt][j] = 0.f;
#pragma unroll
                for (int s = 0; s < 4; s++) {
                    mma16816(sc[nt], qh[s],  kh8[2 * s], kh8[2 * s + 1]);
                    mma16816(sc[nt], qh[s],  kl8[2 * s], kl8[2 * s + 1]);
                    mma16816(sc[nt], qlr[s], kh8[2 * s], kh8[2 * s + 1]);
                }
            }

            const int R0 = wrow0 + (l >> 2);
            if (ks + 64 > wrow0) {
                int colb = ks + ((l & 3) << 1);
#pragma unroll
                for (int nt = 0; nt < 8; nt++) {
                    int c0 = colb + (nt << 3);
                    if (c0     > R0)     sc[nt][0] = -3.0e38f;
                    if (c0 + 1 > R0)     sc[nt][1] = -3.0e38f;
                    if (c0     > R0 + 8) sc[nt][2] = -3.0e38f;
                    if (c0 + 1 > R0 + 8) sc[nt][3] = -3.0e38f;
                }
            }

            float tm0 = -3.0e38f, tm1 = -3.0e38f;
#pragma unroll
            for (int nt = 0; nt < 8; nt++) {
                tm0 = fmaxf(tm0, fmaxf(sc[nt][0], sc[nt][1]));
                tm1 = fmaxf(tm1, fmaxf(sc[nt][2], sc[nt][3]));
            }
            tm0 = fmaxf(tm0, __shfl_xor_sync(0xffffffffu, tm0, 1));
            tm0 = fmaxf(tm0, __shfl_xor_sync(0xffffffffu, tm0, 2));
            tm1 = fmaxf(tm1, __shfl_xor_sync(0xffffffffu, tm1, 1));
            tm1 = fmaxf(tm1, __shfl_xor_sync(0xffffffffu, tm1, 2));
            float mn0 = fmaxf(m0, tm0), mn1 = fmaxf(m1, tm1);
            float c0 = __expf(m0 - mn0), c1 = __expf(m1 - mn1);

            float ps0 = 0.f, ps1 = 0.f;
            uint32_t phi[4][4], plo[4][4];
#pragma unroll
            for (int s = 0; s < 4; s++) {
#pragma unroll
                for (int h = 0; h < 2; h++) {
                    int nt = 2 * s + h;
                    float p0 = __expf(sc[nt][0] - mn0);
                    float p1 = __expf(sc[nt][1] - mn0);
                    float p2 = __expf(sc[nt][2] - mn1);
                    float p3 = __expf(sc[nt][3] - mn1);
                    ps0 += p0 + p1;
                    ps1 += p2 + p3;
                    split2(p0, p1, phi[s][2 * h],     plo[s][2 * h]);
                    split2(p2, p3, phi[s][2 * h + 1], plo[s][2 * h + 1]);
                }
            }
            ps0 += __shfl_xor_sync(0xffffffffu, ps0, 1);
            ps0 += __shfl_xor_sync(0xffffffffu, ps0, 2);
            ps1 += __shfl_xor_sync(0xffffffffu, ps1, 1);
            ps1 += __shfl_xor_sync(0xffffffffu, ps1, 2);
            ls0 = ls0 * c0 + ps0;
            ls1 = ls1 * c1 + ps1;
            m0 = mn0; m1 = mn1;

#pragma unroll
            for (int nt = 0; nt < 8; nt++) {
                o[nt][0] *= c0; o[nt][1] *= c0;
                o[nt][2] *= c1; o[nt][3] *= c1;
            }
#pragma unroll
            for (int nt = 0; nt < 8; nt++) {
                int row = (nt << 3) + brow;
                uint32_t rb = kvb + (uint32_t)row * 128u;
                uint32_t s0 = (uint32_t)((bu       ^ (row & 7)) << 4);
                uint32_t s1 = (uint32_t)(((4 + bu) ^ (row & 7)) << 4);
                uint32_t vh8[8], vl8[8];
                ldsm4(vh8,     rb + A_VHI + s0);
                ldsm4(vh8 + 4, rb + A_VHI + s1);
                ldsm4(vl8,     rb + A_VLO + s0);
                ldsm4(vl8 + 4, rb + A_VLO + s1);
#pragma unroll
                for (int s = 0; s < 4; s++) {
                    mma16816(o[nt], phi[s], vh8[2 * s], vh8[2 * s + 1]);
                    mma16816(o[nt], phi[s], vl8[2 * s], vl8[2 * s + 1]);
                    mma16816(o[nt], plo[s], vh8[2 * s], vh8[2 * s + 1]);
                }
            }
        }
    }

    const float inv0 = 1.f / ls0, inv1 = 1.f / ls1;
    const int R0g = q0 + (w << 4) + (l >> 2);
    float* o0p = out + (((size_t)(b * Tn + R0g)) << 6) + ((l & 3) << 1);
    float* o1p = o0p + (8 << 6);
#pragma unroll
    for (int nt = 0; nt < 8; nt++) {
        *(float2*)(o0p + (nt << 3)) = make_float2(o[nt][0] * inv0, o[nt][1] * inv0);
        *(float2*)(o1p + (nt << 3)) = make_float2(o[nt][2] * inv1, o[nt][3] * inv1);
    }
}

// ===================== launch =====================
extern "C" void kernel_launch(void* const* d_in, const int* in_sizes, int n_in,
                              void* d_out, int out_size)
{
    const float* x  = (const float*)d_in[0];
    const float* WQ = (const float*)d_in[1];
    const float* WK = (const float*)d_in[2];
    const float* WV = (const float*)d_in[3];
    float* out = (float*)d_out;

    cudaFuncSetAttribute(proj_tc_kernel,
                         cudaFuncAttributeMaxDynamicSharedMemorySize, PROJ_SMEM);
    cudaFuncSetAttribute(attn_kernel,
                         cudaFuncAttributeMaxDynamicSharedMemorySize, ATTN_SMEM);

    prep_w<<<18, 256>>>(WQ, WK, WV);
    proj_tc_kernel<<<256, 256, PROJ_SMEM>>>(x);
    attn_kernel<<<512, 128, ATTN_SMEM>>>(out);
}